// round 14
// baseline (speedup 1.0000x reference)
#include <cuda_runtime.h>
#include <cstdint>

// PatchPooling: out[b,p,d] = mean over s in [fr, to) of batch[b,s,d]; empty -> -1
// B=64, S=1024, D=256, P=64. to = inclusive cumsum of patch_lengths, fr = to - len.
//
// One block handles 4 consecutive patches of one batch. 256 threads:
//   slice = tid >> 6 (which of the 4 patches), lane = tid & 63 (which float4 of D).
// Per row each slice reads 64 * 16B = 1024B contiguous -> fully coalesced.

#ifndef PP_B
#define PP_B 64
#endif
#define PP_S 1024
#define PP_D 256
#define PP_P 64
#define PP_D4 (PP_D / 4)          // 64 float4 per row
#define PATCHES_PER_BLOCK 4

__global__ __launch_bounds__(256, 8)
void patch_pooling_kernel(const float4* __restrict__ batch,
                          const int* __restrict__ plen,
                          float4* __restrict__ out)
{
    const int b    = blockIdx.y;           // 0..63
    const int pblk = blockIdx.x;           // 0..15
    const int tid  = threadIdx.x;

    // s_cum[i] = sum of lengths [0..i-1] (exclusive prefix), s_cum[64] = total.
    __shared__ int s_cum[PP_P + 1];

    if (tid < PP_P) {
        s_cum[tid + 1] = plen[b * PP_P + tid];
    }
    if (tid == 0) s_cum[0] = 0;
    __syncthreads();

    if (tid == 0) {
        int acc = 0;
        #pragma unroll
        for (int i = 1; i <= PP_P; i++) {
            acc += s_cum[i];
            s_cum[i] = acc;
        }
    }
    __syncthreads();

    const int slice = tid >> 6;            // 0..3
    const int lane  = tid & 63;            // 0..63 (float4 index in D)
    const int p     = pblk * PATCHES_PER_BLOCK + slice;

    int fr = s_cum[p];
    int to = s_cum[p + 1];
    // clamp to S (defensive; lengths sum to <= 960 here)
    fr = fr < PP_S ? fr : PP_S;
    to = to < PP_S ? to : PP_S;
    const int cnt = to - fr;

    const float4* row = batch + (size_t)b * PP_S * PP_D4 + lane;

    float ax = 0.f, ay = 0.f, az = 0.f, aw = 0.f;
    for (int s = fr; s < to; s++) {
        float4 v = row[(size_t)s * PP_D4];
        ax += v.x; ay += v.y; az += v.z; aw += v.w;
    }

    float4 o;
    if (cnt == 0) {
        o.x = o.y = o.z = o.w = -1.0f;
    } else {
        const float inv = 1.0f / (float)cnt;
        o.x = ax * inv; o.y = ay * inv; o.z = az * inv; o.w = aw * inv;
    }

    out[((size_t)b * PP_P + p) * PP_D4 + lane] = o;
}

extern "C" void kernel_launch(void* const* d_in, const int* in_sizes, int n_in,
                              void* d_out, int out_size)
{
    const float4* batch = (const float4*)d_in[0];       // [B,S,D] fp32
    const int*    plen  = (const int*)d_in[1];          // [B,P] int32
    float4*       out   = (float4*)d_out;               // [B,P,D] fp32

    const int B = in_sizes[1] / PP_P;                   // 64
    dim3 grid(PP_P / PATCHES_PER_BLOCK, B);             // (16, 64)
    patch_pooling_kernel<<<grid, 256>>>(batch, plen, out);
}

// round 15
// speedup vs baseline: 1.0258x; 1.0258x over previous
#include <cuda_runtime.h>
#include <cstdint>

// PatchPooling: out[b,p,d] = mean over s in [fr, to) of batch[b,s,d]; empty -> -1
// B=64, S=1024, D=256, P=64. patch_lengths in [0,16).
//
// One block = 4 consecutive patches of one batch, 256 threads:
//   slice = tid>>6 -> patch, lane = tid&63 -> float4 column of D.
// Row loop fully unrolled to 15 predicated iterations -> all LDG.128
// independent, front-batched for high MLP (DRAM-latency hiding).

#define PP_S 1024
#define PP_D 256
#define PP_P 64
#define PP_D4 (PP_D / 4)          // 64 float4 per row
#define PATCHES_PER_BLOCK 4
#define MAX_LEN 15                // randint(0,16) -> lengths <= 15

__global__ __launch_bounds__(256)
void patch_pooling_kernel(const float4* __restrict__ batch,
                          const int* __restrict__ plen,
                          float4* __restrict__ out)
{
    const int b    = blockIdx.y;           // 0..63
    const int pblk = blockIdx.x;           // 0..15
    const int tid  = threadIdx.x;

    // s_cum[i] = exclusive prefix of lengths; s_cum[64] = total.
    __shared__ int s_cum[PP_P + 1];

    // Warp-0 parallel scan of the 64 lengths (two 32-wide shfl scans).
    if (tid < 32) {
        int a = plen[b * PP_P + tid];           // lengths [0..31]
        int c = plen[b * PP_P + 32 + tid];      // lengths [32..63]
        #pragma unroll
        for (int o = 1; o < 32; o <<= 1) {
            int ta = __shfl_up_sync(0xffffffffu, a, o);
            int tc = __shfl_up_sync(0xffffffffu, c, o);
            if (tid >= o) { a += ta; c += tc; }
        }
        c += __shfl_sync(0xffffffffu, a, 31);   // add total of first half
        s_cum[tid + 1]  = a;
        s_cum[tid + 33] = c;
        if (tid == 0) s_cum[0] = 0;
    }
    __syncthreads();

    const int slice = tid >> 6;            // 0..3
    const int lane  = tid & 63;            // 0..63
    const int p     = pblk * PATCHES_PER_BLOCK + slice;

    int fr = s_cum[p];
    int to = s_cum[p + 1];
    fr = fr < PP_S ? fr : PP_S;            // defensive clamp
    to = to < PP_S ? to : PP_S;
    const int cnt = to - fr;

    const float4* rowp = batch + (size_t)b * PP_S * PP_D4
                               + (size_t)fr * PP_D4 + lane;

    // Fully unrolled predicated loads: up to 15 independent LDG.128.
    float ax = 0.f, ay = 0.f, az = 0.f, aw = 0.f;
    float bx = 0.f, by = 0.f, bz = 0.f, bw = 0.f;  // second chain to shorten deps
    #pragma unroll
    for (int i = 0; i < MAX_LEN; i++) {
        if (i < cnt) {
            float4 v = rowp[(size_t)i * PP_D4];
            if (i & 1) { bx += v.x; by += v.y; bz += v.z; bw += v.w; }
            else       { ax += v.x; ay += v.y; az += v.z; aw += v.w; }
        }
    }
    // Defensive tail for cnt > 15 (cannot occur with this dataset).
    for (int i = MAX_LEN; i < cnt; i++) {
        float4 v = rowp[(size_t)i * PP_D4];
        ax += v.x; ay += v.y; az += v.z; aw += v.w;
    }
    ax += bx; ay += by; az += bz; aw += bw;

    float4 o;
    if (cnt == 0) {
        o.x = o.y = o.z = o.w = -1.0f;
    } else {
        const float inv = 1.0f / (float)cnt;
        o.x = ax * inv; o.y = ay * inv; o.z = az * inv; o.w = aw * inv;
    }

    out[((size_t)b * PP_P + p) * PP_D4 + lane] = o;
}

extern "C" void kernel_launch(void* const* d_in, const int* in_sizes, int n_in,
                              void* d_out, int out_size)
{
    const float4* batch = (const float4*)d_in[0];       // [B,S,D] fp32
    const int*    plen  = (const int*)d_in[1];          // [B,P] int32
    float4*       out   = (float4*)d_out;               // [B,P,D] fp32

    const int B = in_sizes[1] / PP_P;                   // 64
    dim3 grid(PP_P / PATCHES_PER_BLOCK, B);             // (16, 64)
    patch_pooling_kernel<<<grid, 256>>>(batch, plen, out);
}